// round 2
// baseline (speedup 1.0000x reference)
#include <cuda_runtime.h>
#include <math.h>

#define Nn 100000
#define Dd 512
#define Kk 400
#define NCLS 100

// ---------------- scratch (device globals; no allocation allowed) ----------------
__device__ float g_E[(size_t)Nn * Kk];     // exp(C/eps) for current phase (160MB)
__device__ float g_C2[(size_t)Nn * Kk];    // raw cosine sims of phase 2 (160MB)
__device__ float g_alpha[Kk];
__device__ float g_rowsum[Kk];
__device__ float g_w2[Kk];
__device__ float g_coeff[Nn * 4];
__device__ float g_upd[Kk * Dd];
__device__ float g_pn[Kk * Dd];
__device__ float g_negsum[Nn];
__device__ float g_adc[Kk * Kk];
__device__ float g_pconsum;

// ---------------- init ----------------
__global__ void init_kernel() {
    int i = blockIdx.x * blockDim.x + threadIdx.x;
    if (i < Kk * Dd) g_upd[i] = 0.f;
    if (i < Nn) g_negsum[i] = 0.f;
    if (i < Kk) { g_rowsum[i] = 0.f; g_w2[i] = 0.f; }
    if (i == 0) g_pconsum = 0.f;
}

// ---------------- SGEMM: C[n,k] = sum_d A[n,d]*B[k,d], both row-major, ld=512 ----
// BM=128, BN=64, BK=16, 256 threads, 8x4 microtile.
// Epilogue flags: SC store raw C, SE store E=exp(20c), AR accumulate rowsum[k] of E,
// AN accumulate negsum[n] of exp(10c).
template <bool SC, bool SE, bool AR, bool AN>
__global__ void __launch_bounds__(256) sgemm_kernel(
    const float* __restrict__ A, const float* __restrict__ Bm,
    float* __restrict__ Cb, float* __restrict__ Eb,
    float* __restrict__ rowsum, int Mr, int Nc)
{
    __shared__ float As[16][128];
    __shared__ float Bs[16][64];
    __shared__ float colacc[64];
    __shared__ float rowacc[128];

    const int tid = threadIdx.x;
    const int bm = blockIdx.y * 128;
    const int bn = blockIdx.x * 64;
    const int tx = tid & 15;      // -> cols 4*tx..4*tx+3
    const int ty = tid >> 4;      // -> rows 8*ty..8*ty+7

    float acc[8][4];
#pragma unroll
    for (int i = 0; i < 8; i++)
#pragma unroll
        for (int j = 0; j < 4; j++) acc[i][j] = 0.f;

    const int alr = tid >> 1, alc = (tid & 1) * 8;   // A loader: row, col base
    const int blr = tid >> 2, blc = (tid & 3) * 4;   // B loader
    const bool arow_ok = (bm + alr) < Mr;
    const bool brow_ok = (bn + blr) < Nc;
    const float* Aptr = A + (size_t)(bm + alr) * Dd + alc;
    const float* Bptr = Bm + (size_t)(bn + blr) * Dd + blc;

    for (int dk = 0; dk < Dd; dk += 16) {
        float4 a0 = {0,0,0,0}, a1 = {0,0,0,0}, b0 = {0,0,0,0};
        if (arow_ok) {
            a0 = *(const float4*)(Aptr + dk);
            a1 = *(const float4*)(Aptr + dk + 4);
        }
        if (brow_ok) b0 = *(const float4*)(Bptr + dk);

        As[alc + 0][alr] = a0.x; As[alc + 1][alr] = a0.y;
        As[alc + 2][alr] = a0.z; As[alc + 3][alr] = a0.w;
        As[alc + 4][alr] = a1.x; As[alc + 5][alr] = a1.y;
        As[alc + 6][alr] = a1.z; As[alc + 7][alr] = a1.w;
        Bs[blc + 0][blr] = b0.x; Bs[blc + 1][blr] = b0.y;
        Bs[blc + 2][blr] = b0.z; Bs[blc + 3][blr] = b0.w;
        __syncthreads();

#pragma unroll
        for (int dd = 0; dd < 16; dd++) {
            float4 av0 = *(const float4*)&As[dd][ty * 8];
            float4 av1 = *(const float4*)&As[dd][ty * 8 + 4];
            float4 bv  = *(const float4*)&Bs[dd][tx * 4];
            float ar[8] = {av0.x, av0.y, av0.z, av0.w, av1.x, av1.y, av1.z, av1.w};
            float br[4] = {bv.x, bv.y, bv.z, bv.w};
#pragma unroll
            for (int i = 0; i < 8; i++)
#pragma unroll
                for (int j = 0; j < 4; j++)
                    acc[i][j] = fmaf(ar[i], br[j], acc[i][j]);
        }
        __syncthreads();
    }

    // ---- epilogue ----
    if (AR) for (int i = tid; i < 64; i += 256) colacc[i] = 0.f;
    if (AN) for (int i = tid; i < 128; i += 256) rowacc[i] = 0.f;
    if (AR || AN) __syncthreads();

    float colp[4] = {0.f, 0.f, 0.f, 0.f};
    float rowp[8] = {0.f, 0.f, 0.f, 0.f, 0.f, 0.f, 0.f, 0.f};

#pragma unroll
    for (int i = 0; i < 8; i++) {
        int n = bm + ty * 8 + i;
        if (n >= Mr) continue;
#pragma unroll
        for (int j = 0; j < 4; j++) {
            int k = bn + tx * 4 + j;
            if (k >= Nc) continue;
            float c = acc[i][j];
            if (SC) Cb[(size_t)n * Kk + k] = c;
            if (SE) {
                float x = __expf(10.f * c);   // exp(c/TEMP)
                float e = x * x;              // exp(c/EPS)
                Eb[(size_t)n * Kk + k] = e;
                if (AR) colp[j] += e;
                if (AN) rowp[i] += x;
            }
        }
    }
    if (AR) {
#pragma unroll
        for (int j = 0; j < 4; j++)
            if (bn + tx * 4 + j < Nc) atomicAdd(&colacc[tx * 4 + j], colp[j]);
    }
    if (AN) {
#pragma unroll
        for (int i = 0; i < 8; i++)
            if (bm + ty * 8 + i < Mr) atomicAdd(&rowacc[ty * 8 + i], rowp[i]);
    }
    if (AR || AN) {
        __syncthreads();
        if (AR) for (int i = tid; i < 64; i += 256) {
            int k = bn + i;
            if (k < Nc) atomicAdd(&rowsum[k], colacc[i]);
        }
        if (AN) for (int i = tid; i < 128; i += 256) {
            int n = bm + i;
            if (n < Mr) atomicAdd(&g_negsum[n], rowacc[i]);
        }
    }
}

// ---------------- alpha[k] = 1/(K * rowsum[k]); reset rowsum ----------------
__global__ void alpha_kernel() {
    int k = blockIdx.x * blockDim.x + threadIdx.x;
    if (k < Kk) {
        float rs = g_rowsum[k];
        g_alpha[k] = 1.f / (400.f * fmaxf(rs, 1e-12f));
        g_rowsum[k] = 0.f;
    }
}

// ---------------- fused Sinkhorn pass: col-normalize step + next row-sum ----------
// per sample n: b = sum_k E[n,k]*alpha[k]; beta = 1/(N*b); rowsum[k] += E[n,k]*beta
__global__ void __launch_bounds__(256) sink_pass(const float* __restrict__ E,
                                                 float* __restrict__ rowsum_out) {
    __shared__ float s_alpha[Kk];
    __shared__ float s_acc[Kk];
    for (int i = threadIdx.x; i < Kk; i += 256) { s_alpha[i] = g_alpha[i]; s_acc[i] = 0.f; }
    __syncthreads();

    const int lane = threadIdx.x & 31;
    const int warp = threadIdx.x >> 5;
    const int gw = blockIdx.x * 8 + warp;
    float racc[13];
#pragma unroll
    for (int j = 0; j < 13; j++) racc[j] = 0.f;

    const int n0 = gw * 8;
    for (int r = 0; r < 8; r++) {
        int n = n0 + r;
        if (n >= Nn) break;
        const float* row = E + (size_t)n * Kk;
        float e[13];
        float s = 0.f;
#pragma unroll
        for (int j = 0; j < 13; j++) {
            int k = lane + 32 * j;
            float v = (k < Kk) ? row[k] : 0.f;
            e[j] = v;
            s += v * ((k < Kk) ? s_alpha[k] : 0.f);
        }
#pragma unroll
        for (int o = 16; o; o >>= 1) s += __shfl_xor_sync(0xffffffffu, s, o);
        float beta = 1.f / ((float)Nn * fmaxf(s, 1e-30f));
#pragma unroll
        for (int j = 0; j < 13; j++) racc[j] = fmaf(e[j], beta, racc[j]);
    }
#pragma unroll
    for (int j = 0; j < 13; j++) {
        int k = lane + 32 * j;
        if (k < Kk) atomicAdd(&s_acc[k], racc[j]);
    }
    __syncthreads();
    for (int i = threadIdx.x; i < Kk; i += 256) atomicAdd(&rowsum_out[i], s_acc[i]);
}

// ---------------- per-sample transport coeffs + column sums w2 ----------------
__global__ void coeff_kernel(const int* __restrict__ labels) {
    __shared__ float sacc[Kk];
    for (int i = threadIdx.x; i < Kk; i += blockDim.x) sacc[i] = 0.f;
    __syncthreads();
    int n = blockIdx.x * blockDim.x + threadIdx.x;
    int l = 0;
    float c4[4] = {0.f, 0.f, 0.f, 0.f};
    if (n < Nn) {
        l = labels[n];
        const float* row = g_E + (size_t)n * Kk;
        float q[4], s = 0.f;
#pragma unroll
        for (int p = 0; p < 4; p++) {
            int k = l + 100 * p;
            q[p] = g_alpha[k] * row[k];
            s += q[p];
        }
        float inv = 1.f / fmaxf(s, 1e-30f);
#pragma unroll
        for (int p = 0; p < 4; p++) {
            float c = q[p] * inv;
            c4[p] = c;
            g_coeff[n * 4 + p] = c;
        }
    }
    if (n < Nn) {
#pragma unroll
        for (int p = 0; p < 4; p++) atomicAdd(&sacc[l + 100 * p], c4[p]);
    }
    __syncthreads();
    for (int i = threadIdx.x; i < Kk; i += blockDim.x) atomicAdd(&g_w2[i], sacc[i]);
}

// ---------------- scatter: upd[k,d] += (coeff/w2[k]) * f[n,d] ----------------
// grid.x = 8 column groups of 64, grid.y = n-chunks; smem acc[400][64]
__global__ void __launch_bounds__(256) scatter_kernel(const float* __restrict__ feats,
                                                      const int* __restrict__ labels,
                                                      int nchunks) {
    extern __shared__ float sm[];
    float* acc = sm;               // 400*64
    float* winv = sm + 400 * 64;   // 400
    const int tid = threadIdx.x;
    for (int i = tid; i < 400 * 64; i += 256) acc[i] = 0.f;
    for (int i = tid; i < Kk; i += 256) winv[i] = 1.f / fmaxf(g_w2[i], 1e-12f);
    __syncthreads();

    const int d = tid & 63;
    const int sub = tid >> 6;          // p index 0..3
    const int d0 = blockIdx.x * 64;
    const int CH = (Nn + nchunks - 1) / nchunks;
    const int nb = blockIdx.y * CH;
    const int ne = (nb + CH < Nn) ? (nb + CH) : Nn;

    for (int n = nb; n < ne; n++) {
        int l = labels[n];
        float f = feats[(size_t)n * Dd + d0 + d];
        int k = l + 100 * sub;
        float c = g_coeff[n * 4 + sub] * winv[k];
        acc[k * 64 + d] += c * f;
    }
    __syncthreads();
    for (int i = tid; i < 400 * 64; i += 256)
        atomicAdd(&g_upd[(i >> 6) * Dd + d0 + (i & 63)], acc[i]);
}

// ---------------- protos_new = l2norm(0.99*protos + 0.01*upd) ----------------
__global__ void pnew_kernel(const float* __restrict__ protos) {
    int k = blockIdx.x;
    int tid = threadIdx.x;  // 128
    float v[4];
    float ss = 0.f;
#pragma unroll
    for (int j = 0; j < 4; j++) {
        int di = tid + 128 * j;
        float x = 0.99f * protos[k * Dd + di] + 0.01f * g_upd[k * Dd + di];
        v[j] = x;
        ss += x * x;
    }
    __shared__ float red[4];
#pragma unroll
    for (int o = 16; o; o >>= 1) ss += __shfl_xor_sync(0xffffffffu, ss, o);
    if ((tid & 31) == 0) red[tid >> 5] = ss;
    __syncthreads();
    float tot = red[0] + red[1] + red[2] + red[3];
    float inv = 1.f / fmaxf(sqrtf(tot), 1e-12f);
#pragma unroll
    for (int j = 0; j < 4; j++)
        g_pn[k * Dd + tid + 128 * j] = v[j] * inv;
}

// ---------------- proto contrast: one block per proto row ----------------
__global__ void pcon_kernel() {
    int k = blockIdx.x;
    int tid = threadIdx.x;  // 128
    const float* row = g_adc + k * Kk;
    __shared__ float rbuf[4];
    __shared__ float mxs;

    float mx = -1e30f;
    for (int j = tid; j < Kk; j += 128) mx = fmaxf(mx, 2.f * row[j]);
#pragma unroll
    for (int o = 16; o; o >>= 1) mx = fmaxf(mx, __shfl_xor_sync(0xffffffffu, mx, o));
    if ((tid & 31) == 0) rbuf[tid >> 5] = mx;
    __syncthreads();
    if (tid == 0) mxs = fmaxf(fmaxf(rbuf[0], rbuf[1]), fmaxf(rbuf[2], rbuf[3]));
    __syncthreads();
    mx = mxs;

    float se = 0.f, pp = 0.f;
    int cls = k % 100;
    for (int j = tid; j < Kk; j += 128) {
        float lg = 2.f * row[j] - mx;
        if (j != k) {
            se += __expf(lg);
            if (j % 100 == cls) pp += lg;
        }
    }
#pragma unroll
    for (int o = 16; o; o >>= 1) {
        se += __shfl_xor_sync(0xffffffffu, se, o);
        pp += __shfl_xor_sync(0xffffffffu, pp, o);
    }
    __shared__ float sbuf[4], pbuf[4];
    if ((tid & 31) == 0) { sbuf[tid >> 5] = se; pbuf[tid >> 5] = pp; }
    __syncthreads();
    if (tid == 0) {
        float sT = sbuf[0] + sbuf[1] + sbuf[2] + sbuf[3];
        float pT = pbuf[0] + pbuf[1] + pbuf[2] + pbuf[3];
        atomicAdd(&g_pconsum, pT * (1.f / 3.f) - logf(sT));
    }
}

// ---------------- final per-sample loss ----------------
__global__ void final_kernel(const int* __restrict__ labels, float* __restrict__ out) {
    int n = blockIdx.x * blockDim.x + threadIdx.x;
    if (n >= Nn) return;
    int l = labels[n];
    const float* row = g_C2 + (size_t)n * Kk;
    float num = 0.f, den = 0.f;
#pragma unroll
    for (int p = 0; p < 4; p++) {
        int k = l + 100 * p;
        float c = row[k];
        float q = g_alpha[k] * __expf(20.f * c);
        num += q * (10.f * c);
        den += q;
    }
    float pos = num / fmaxf(den, 1e-30f);
    float neg = logf(g_negsum[n]);
    float pcon = -g_pconsum * (1.f / 400.f);
    out[n] = -(pos - neg) + pcon;
}

// ---------------- launch ----------------
extern "C" void kernel_launch(void* const* d_in, const int* in_sizes, int n_in,
                              void* d_out, int out_size) {
    const float* feats  = (const float*)d_in[0];
    const float* protos = (const float*)d_in[1];
    const int*   labels = (const int*)d_in[2];
    float* out = (float*)d_out;

    float *pE, *pC2, *pPN, *pADC, *pRS;
    cudaGetSymbolAddress((void**)&pE,  g_E);
    cudaGetSymbolAddress((void**)&pC2, g_C2);
    cudaGetSymbolAddress((void**)&pPN, g_pn);
    cudaGetSymbolAddress((void**)&pADC, g_adc);
    cudaGetSymbolAddress((void**)&pRS, g_rowsum);

    const int SMEM_SCATTER = (400 * 64 + 400) * 4;
    cudaFuncSetAttribute(scatter_kernel, cudaFuncAttributeMaxDynamicSharedMemorySize,
                         SMEM_SCATTER);

    // 0) zero accumulators
    init_kernel<<<(Kk * Dd + 255) / 256, 256>>>();

    dim3 g1((Kk + 63) / 64, (Nn + 127) / 128);

    // ---------- phase 1 (mle / prototype update) ----------
    // GEMM1: E1 = exp(20 * feats@protos^T); rowsum = sum_n E1 (Sinkhorn iter1 row step)
    sgemm_kernel<false, true, true, false><<<g1, 256>>>(feats, protos, nullptr, pE, pRS,
                                                        Nn, Kk);
    alpha_kernel<<<2, 256>>>();                      // alpha1
    sink_pass<<<(Nn + 63) / 64, 256>>>(pE, pRS);     // iter1 col + iter2 row
    alpha_kernel<<<2, 256>>>();                      // alpha2
    sink_pass<<<(Nn + 63) / 64, 256>>>(pE, pRS);     // iter2 col + iter3 row
    alpha_kernel<<<2, 256>>>();                      // alpha3 (rowsum reset for phase 2)

    coeff_kernel<<<(Nn + 255) / 256, 256>>>(labels);
    {
        dim3 gs(8, 32);
        scatter_kernel<<<gs, 256, SMEM_SCATTER>>>(feats, labels, 32);
    }
    pnew_kernel<<<Kk, 128>>>(protos);

    // ---------- phase 2 (g_con) ----------
    // GEMM2: C2 + E2; rowsum = Sinkhorn iter1 row step; negsum = sum_k exp(10*C2)
    sgemm_kernel<true, true, true, true><<<g1, 256>>>(feats, pPN, pC2, pE, pRS, Nn, Kk);
    alpha_kernel<<<2, 256>>>();
    sink_pass<<<(Nn + 63) / 64, 256>>>(pE, pRS);
    alpha_kernel<<<2, 256>>>();
    sink_pass<<<(Nn + 63) / 64, 256>>>(pE, pRS);
    alpha_kernel<<<2, 256>>>();                      // alpha3' used by final_kernel

    // ---------- proto contrast ----------
    {
        dim3 ga((Kk + 63) / 64, (Kk + 127) / 128);
        sgemm_kernel<true, false, false, false><<<ga, 256>>>(pPN, pPN, pADC, nullptr,
                                                             nullptr, Kk, Kk);
    }
    pcon_kernel<<<Kk, 128>>>();

    // ---------- final ----------
    final_kernel<<<(Nn + 255) / 256, 256>>>(labels, out);
}

// round 3
// speedup vs baseline: 1.0425x; 1.0425x over previous
#include <cuda_runtime.h>
#include <math.h>

#define Nn 100000
#define Dd 512
#define Kk 400
#define NCLS 100

// ---------------- scratch (device globals; no allocation allowed) ----------------
__device__ float g_E[(size_t)Nn * Kk];     // exp(C/eps) for current phase (160MB)
__device__ float g_C2[(size_t)Nn * Kk];    // raw cosine sims of phase 2 (160MB)
__device__ float g_alpha[Kk];
__device__ float g_rowsum[Kk];
__device__ float g_w2[Kk];
__device__ float g_coeff[Nn * 4];
__device__ float g_upd[Kk * Dd];
__device__ float g_pn[Kk * Dd];
__device__ float g_negsum[Nn];
__device__ float g_adc[Kk * Kk];
__device__ float g_pconsum;

// ---------------- init ----------------
__global__ void init_kernel() {
    int i = blockIdx.x * blockDim.x + threadIdx.x;
    if (i < Kk * Dd) g_upd[i] = 0.f;
    if (i < Nn) g_negsum[i] = 0.f;
    if (i < Kk) { g_rowsum[i] = 0.f; g_w2[i] = 0.f; }
    if (i == 0) g_pconsum = 0.f;
}

// ---------------- SGEMM: C[n,k] = sum_d A[n,d]*B[k,d], both row-major, ld=512 ----
// BM=128, BN=64, BK=16, 256 threads, 8x4 microtile.
// Epilogue flags: SC store raw C, SE store E=exp(20c), AR accumulate rowsum[k] of E,
// AN accumulate negsum[n] of exp(10c).
template <bool SC, bool SE, bool AR, bool AN>
__global__ void __launch_bounds__(256) sgemm_kernel(
    const float* __restrict__ A, const float* __restrict__ Bm,
    float* __restrict__ Cb, float* __restrict__ Eb,
    float* __restrict__ rowsum, int Mr, int Nc)
{
    __shared__ float As[16][128];
    __shared__ float Bs[16][64];
    __shared__ float colacc[64];
    __shared__ float rowacc[128];

    const int tid = threadIdx.x;
    const int bm = blockIdx.y * 128;
    const int bn = blockIdx.x * 64;
    const int tx = tid & 15;      // -> cols 4*tx..4*tx+3
    const int ty = tid >> 4;      // -> rows 8*ty..8*ty+7

    float acc[8][4];
#pragma unroll
    for (int i = 0; i < 8; i++)
#pragma unroll
        for (int j = 0; j < 4; j++) acc[i][j] = 0.f;

    const int alr = tid >> 1, alc = (tid & 1) * 8;   // A loader: row, col base
    const int blr = tid >> 2, blc = (tid & 3) * 4;   // B loader
    const bool arow_ok = (bm + alr) < Mr;
    const bool brow_ok = (bn + blr) < Nc;
    const float* Aptr = A + (size_t)(bm + alr) * Dd + alc;
    const float* Bptr = Bm + (size_t)(bn + blr) * Dd + blc;

    for (int dk = 0; dk < Dd; dk += 16) {
        float4 a0 = {0,0,0,0}, a1 = {0,0,0,0}, b0 = {0,0,0,0};
        if (arow_ok) {
            a0 = *(const float4*)(Aptr + dk);
            a1 = *(const float4*)(Aptr + dk + 4);
        }
        if (brow_ok) b0 = *(const float4*)(Bptr + dk);

        As[alc + 0][alr] = a0.x; As[alc + 1][alr] = a0.y;
        As[alc + 2][alr] = a0.z; As[alc + 3][alr] = a0.w;
        As[alc + 4][alr] = a1.x; As[alc + 5][alr] = a1.y;
        As[alc + 6][alr] = a1.z; As[alc + 7][alr] = a1.w;
        Bs[blc + 0][blr] = b0.x; Bs[blc + 1][blr] = b0.y;
        Bs[blc + 2][blr] = b0.z; Bs[blc + 3][blr] = b0.w;
        __syncthreads();

#pragma unroll
        for (int dd = 0; dd < 16; dd++) {
            float4 av0 = *(const float4*)&As[dd][ty * 8];
            float4 av1 = *(const float4*)&As[dd][ty * 8 + 4];
            float4 bv  = *(const float4*)&Bs[dd][tx * 4];
            float ar[8] = {av0.x, av0.y, av0.z, av0.w, av1.x, av1.y, av1.z, av1.w};
            float br[4] = {bv.x, bv.y, bv.z, bv.w};
#pragma unroll
            for (int i = 0; i < 8; i++)
#pragma unroll
                for (int j = 0; j < 4; j++)
                    acc[i][j] = fmaf(ar[i], br[j], acc[i][j]);
        }
        __syncthreads();
    }

    // ---- epilogue ----
    if (AR) for (int i = tid; i < 64; i += 256) colacc[i] = 0.f;
    if (AN) for (int i = tid; i < 128; i += 256) rowacc[i] = 0.f;
    if (AR || AN) __syncthreads();

    float colp[4] = {0.f, 0.f, 0.f, 0.f};
    float rowp[8] = {0.f, 0.f, 0.f, 0.f, 0.f, 0.f, 0.f, 0.f};

#pragma unroll
    for (int i = 0; i < 8; i++) {
        int n = bm + ty * 8 + i;
        if (n >= Mr) continue;
#pragma unroll
        for (int j = 0; j < 4; j++) {
            int k = bn + tx * 4 + j;
            if (k >= Nc) continue;
            float c = acc[i][j];
            if (SC) Cb[(size_t)n * Kk + k] = c;
            if (SE) {
                float x = __expf(10.f * c);   // exp(c/TEMP)
                float e = x * x;              // exp(c/EPS)
                Eb[(size_t)n * Kk + k] = e;
                if (AR) colp[j] += e;
                if (AN) rowp[i] += x;
            }
        }
    }
    if (AR) {
#pragma unroll
        for (int j = 0; j < 4; j++)
            if (bn + tx * 4 + j < Nc) atomicAdd(&colacc[tx * 4 + j], colp[j]);
    }
    if (AN) {
#pragma unroll
        for (int i = 0; i < 8; i++)
            if (bm + ty * 8 + i < Mr) atomicAdd(&rowacc[ty * 8 + i], rowp[i]);
    }
    if (AR || AN) {
        __syncthreads();
        if (AR) for (int i = tid; i < 64; i += 256) {
            int k = bn + i;
            if (k < Nc) atomicAdd(&rowsum[k], colacc[i]);
        }
        if (AN) for (int i = tid; i < 128; i += 256) {
            int n = bm + i;
            if (n < Mr) atomicAdd(&g_negsum[n], rowacc[i]);
        }
    }
}

// ---------------- alpha[k] = 1/(K * rowsum[k]); reset rowsum ----------------
__global__ void alpha_kernel() {
    int k = blockIdx.x * blockDim.x + threadIdx.x;
    if (k < Kk) {
        float rs = g_rowsum[k];
        g_alpha[k] = 1.f / (400.f * fmaxf(rs, 1e-12f));
        g_rowsum[k] = 0.f;
    }
}

// ---------------- fused Sinkhorn pass: col-normalize step + next row-sum ----------
// per sample n: b = sum_k E[n,k]*alpha[k]; beta = 1/(N*b); rowsum[k] += E[n,k]*beta
__global__ void __launch_bounds__(256) sink_pass(const float* __restrict__ E,
                                                 float* __restrict__ rowsum_out) {
    __shared__ float s_alpha[Kk];
    __shared__ float s_acc[Kk];
    for (int i = threadIdx.x; i < Kk; i += 256) { s_alpha[i] = g_alpha[i]; s_acc[i] = 0.f; }
    __syncthreads();

    const int lane = threadIdx.x & 31;
    const int warp = threadIdx.x >> 5;
    const int gw = blockIdx.x * 8 + warp;
    float racc[13];
#pragma unroll
    for (int j = 0; j < 13; j++) racc[j] = 0.f;

    const int n0 = gw * 8;
    for (int r = 0; r < 8; r++) {
        int n = n0 + r;
        if (n >= Nn) break;
        const float* row = E + (size_t)n * Kk;
        float e[13];
        float s = 0.f;
#pragma unroll
        for (int j = 0; j < 13; j++) {
            int k = lane + 32 * j;
            float v = (k < Kk) ? row[k] : 0.f;
            e[j] = v;
            s += v * ((k < Kk) ? s_alpha[k] : 0.f);
        }
#pragma unroll
        for (int o = 16; o; o >>= 1) s += __shfl_xor_sync(0xffffffffu, s, o);
        float beta = 1.f / ((float)Nn * fmaxf(s, 1e-30f));
#pragma unroll
        for (int j = 0; j < 13; j++) racc[j] = fmaf(e[j], beta, racc[j]);
    }
#pragma unroll
    for (int j = 0; j < 13; j++) {
        int k = lane + 32 * j;
        if (k < Kk) atomicAdd(&s_acc[k], racc[j]);
    }
    __syncthreads();
    for (int i = threadIdx.x; i < Kk; i += 256) atomicAdd(&rowsum_out[i], s_acc[i]);
}

// ---------------- per-sample transport coeffs + column sums w2 ----------------
__global__ void coeff_kernel(const int* __restrict__ labels) {
    __shared__ float sacc[Kk];
    for (int i = threadIdx.x; i < Kk; i += blockDim.x) sacc[i] = 0.f;
    __syncthreads();
    int n = blockIdx.x * blockDim.x + threadIdx.x;
    int l = 0;
    float c4[4] = {0.f, 0.f, 0.f, 0.f};
    if (n < Nn) {
        l = labels[n];
        const float* row = g_E + (size_t)n * Kk;
        float q[4], s = 0.f;
#pragma unroll
        for (int p = 0; p < 4; p++) {
            int k = l + 100 * p;
            q[p] = g_alpha[k] * row[k];
            s += q[p];
        }
        float inv = 1.f / fmaxf(s, 1e-30f);
#pragma unroll
        for (int p = 0; p < 4; p++) {
            float c = q[p] * inv;
            c4[p] = c;
            g_coeff[n * 4 + p] = c;
        }
    }
    if (n < Nn) {
#pragma unroll
        for (int p = 0; p < 4; p++) atomicAdd(&sacc[l + 100 * p], c4[p]);
    }
    __syncthreads();
    for (int i = threadIdx.x; i < Kk; i += blockDim.x) atomicAdd(&g_w2[i], sacc[i]);
}

// ---------------- scatter: upd[k,d] += (coeff/w2[k]) * f[n,d] ----------------
// grid.x = 8 column groups of 64, grid.y = n-chunks; smem acc[400][64]
__global__ void __launch_bounds__(256) scatter_kernel(const float* __restrict__ feats,
                                                      const int* __restrict__ labels,
                                                      int nchunks) {
    extern __shared__ float sm[];
    float* acc = sm;               // 400*64
    float* winv = sm + 400 * 64;   // 400
    const int tid = threadIdx.x;
    for (int i = tid; i < 400 * 64; i += 256) acc[i] = 0.f;
    for (int i = tid; i < Kk; i += 256) winv[i] = 1.f / fmaxf(g_w2[i], 1e-12f);
    __syncthreads();

    const int d = tid & 63;
    const int sub = tid >> 6;          // p index 0..3
    const int d0 = blockIdx.x * 64;
    const int CH = (Nn + nchunks - 1) / nchunks;
    const int nb = blockIdx.y * CH;
    const int ne = (nb + CH < Nn) ? (nb + CH) : Nn;

    for (int n = nb; n < ne; n++) {
        int l = labels[n];
        float f = feats[(size_t)n * Dd + d0 + d];
        int k = l + 100 * sub;
        float c = g_coeff[n * 4 + sub] * winv[k];
        acc[k * 64 + d] += c * f;
    }
    __syncthreads();
    for (int i = tid; i < 400 * 64; i += 256)
        atomicAdd(&g_upd[(i >> 6) * Dd + d0 + (i & 63)], acc[i]);
}

// ---------------- protos_new = l2norm(0.99*protos + 0.01*upd) ----------------
__global__ void pnew_kernel(const float* __restrict__ protos) {
    int k = blockIdx.x;
    int tid = threadIdx.x;  // 128
    float v[4];
    float ss = 0.f;
#pragma unroll
    for (int j = 0; j < 4; j++) {
        int di = tid + 128 * j;
        float x = 0.99f * protos[k * Dd + di] + 0.01f * g_upd[k * Dd + di];
        v[j] = x;
        ss += x * x;
    }
    __shared__ float red[4];
#pragma unroll
    for (int o = 16; o; o >>= 1) ss += __shfl_xor_sync(0xffffffffu, ss, o);
    if ((tid & 31) == 0) red[tid >> 5] = ss;
    __syncthreads();
    float tot = red[0] + red[1] + red[2] + red[3];
    float inv = 1.f / fmaxf(sqrtf(tot), 1e-12f);
#pragma unroll
    for (int j = 0; j < 4; j++)
        g_pn[k * Dd + tid + 128 * j] = v[j] * inv;
}

// ---------------- proto contrast: one block per proto row ----------------
__global__ void pcon_kernel() {
    int k = blockIdx.x;
    int tid = threadIdx.x;  // 128
    const float* row = g_adc + k * Kk;
    __shared__ float rbuf[4];
    __shared__ float mxs;

    float mx = -1e30f;
    for (int j = tid; j < Kk; j += 128) mx = fmaxf(mx, 2.f * row[j]);
#pragma unroll
    for (int o = 16; o; o >>= 1) mx = fmaxf(mx, __shfl_xor_sync(0xffffffffu, mx, o));
    if ((tid & 31) == 0) rbuf[tid >> 5] = mx;
    __syncthreads();
    if (tid == 0) mxs = fmaxf(fmaxf(rbuf[0], rbuf[1]), fmaxf(rbuf[2], rbuf[3]));
    __syncthreads();
    mx = mxs;

    float se = 0.f, pp = 0.f;
    int cls = k % 100;
    for (int j = tid; j < Kk; j += 128) {
        float lg = 2.f * row[j] - mx;
        if (j != k) {
            se += __expf(lg);
            if (j % 100 == cls) pp += lg;
        }
    }
#pragma unroll
    for (int o = 16; o; o >>= 1) {
        se += __shfl_xor_sync(0xffffffffu, se, o);
        pp += __shfl_xor_sync(0xffffffffu, pp, o);
    }
    __shared__ float sbuf[4], pbuf[4];
    if ((tid & 31) == 0) { sbuf[tid >> 5] = se; pbuf[tid >> 5] = pp; }
    __syncthreads();
    if (tid == 0) {
        float sT = sbuf[0] + sbuf[1] + sbuf[2] + sbuf[3];
        float pT = pbuf[0] + pbuf[1] + pbuf[2] + pbuf[3];
        atomicAdd(&g_pconsum, pT * (1.f / 3.f) - logf(sT));
    }
}

// ---------------- final per-sample loss ----------------
__global__ void final_kernel(const int* __restrict__ labels, float* __restrict__ out) {
    int n = blockIdx.x * blockDim.x + threadIdx.x;
    if (n >= Nn) return;
    int l = labels[n];
    const float* row = g_C2 + (size_t)n * Kk;
    float num = 0.f, den = 0.f;
#pragma unroll
    for (int p = 0; p < 4; p++) {
        int k = l + 100 * p;
        float c = row[k];
        float q = g_alpha[k] * __expf(20.f * c);
        num += q * (10.f * c);
        den += q;
    }
    float pos = num / fmaxf(den, 1e-30f);
    float neg = logf(g_negsum[n]);
    float pcon = -g_pconsum * (1.f / 400.f);
    out[n] = -(pos - neg) + pcon;
}

// ---------------- launch ----------------
extern "C" void kernel_launch(void* const* d_in, const int* in_sizes, int n_in,
                              void* d_out, int out_size) {
    const float* feats  = (const float*)d_in[0];
    const float* protos = (const float*)d_in[1];
    const int*   labels = (const int*)d_in[2];
    float* out = (float*)d_out;

    float *pE, *pC2, *pPN, *pADC, *pRS;
    cudaGetSymbolAddress((void**)&pE,  g_E);
    cudaGetSymbolAddress((void**)&pC2, g_C2);
    cudaGetSymbolAddress((void**)&pPN, g_pn);
    cudaGetSymbolAddress((void**)&pADC, g_adc);
    cudaGetSymbolAddress((void**)&pRS, g_rowsum);

    const int SMEM_SCATTER = (400 * 64 + 400) * 4;
    cudaFuncSetAttribute(scatter_kernel, cudaFuncAttributeMaxDynamicSharedMemorySize,
                         SMEM_SCATTER);

    // 0) zero accumulators
    init_kernel<<<(Kk * Dd + 255) / 256, 256>>>();

    dim3 g1((Kk + 63) / 64, (Nn + 127) / 128);

    // ---------- phase 1 (mle / prototype update) ----------
    // GEMM1: E1 = exp(20 * feats@protos^T); rowsum = sum_n E1 (Sinkhorn iter1 row step)
    sgemm_kernel<false, true, true, false><<<g1, 256>>>(feats, protos, nullptr, pE, pRS,
                                                        Nn, Kk);
    alpha_kernel<<<2, 256>>>();                      // alpha1
    sink_pass<<<(Nn + 63) / 64, 256>>>(pE, pRS);     // iter1 col + iter2 row
    alpha_kernel<<<2, 256>>>();                      // alpha2
    sink_pass<<<(Nn + 63) / 64, 256>>>(pE, pRS);     // iter2 col + iter3 row
    alpha_kernel<<<2, 256>>>();                      // alpha3 (rowsum reset for phase 2)

    coeff_kernel<<<(Nn + 255) / 256, 256>>>(labels);
    {
        dim3 gs(8, 32);
        scatter_kernel<<<gs, 256, SMEM_SCATTER>>>(feats, labels, 32);
    }
    pnew_kernel<<<Kk, 128>>>(protos);

    // ---------- phase 2 (g_con) ----------
    // GEMM2: C2 + E2; rowsum = Sinkhorn iter1 row step; negsum = sum_k exp(10*C2)
    sgemm_kernel<true, true, true, true><<<g1, 256>>>(feats, pPN, pC2, pE, pRS, Nn, Kk);
    alpha_kernel<<<2, 256>>>();
    sink_pass<<<(Nn + 63) / 64, 256>>>(pE, pRS);
    alpha_kernel<<<2, 256>>>();
    sink_pass<<<(Nn + 63) / 64, 256>>>(pE, pRS);
    alpha_kernel<<<2, 256>>>();                      // alpha3' used by final_kernel

    // ---------- proto contrast ----------
    {
        dim3 ga((Kk + 63) / 64, (Kk + 127) / 128);
        sgemm_kernel<true, false, false, false><<<ga, 256>>>(pPN, pPN, pADC, nullptr,
                                                             nullptr, Kk, Kk);
    }
    pcon_kernel<<<Kk, 128>>>();

    // ---------- final ----------
    final_kernel<<<(Nn + 255) / 256, 256>>>(labels, out);
}

// round 9
// speedup vs baseline: 1.4613x; 1.4017x over previous
#include <cuda_runtime.h>
#include <cuda_bf16.h>
#include <math.h>
#include <stdint.h>

#define Nn 100000
#define Dd 512
#define Kk 400

// ---------------- scratch (device globals; no allocation allowed) ----------------
__device__ float g_E[(size_t)Nn * Kk];     // exp(C/eps) for current phase (160MB)
__device__ float g_alpha[Kk];
__device__ float g_rowsum[Kk];
__device__ float g_w2[Kk];
__device__ float g_coeff[Nn * 4];
__device__ float g_upd[Kk * Dd];
__device__ float g_pn[Kk * Dd];
__device__ float g_negsum[Nn];
__device__ float g_adc[Kk * Kk];
__device__ float g_e4[Nn * 4];             // phase1 E at the 4 class protos
__device__ float g_c4[Nn * 4];             // phase2 raw cosine at the 4 class protos
__device__ float g_pconsum;

__device__ __forceinline__ uint32_t pack2(float lo, float hi) {
    uint32_t r;
    asm("cvt.rn.bf16x2.f32 %0, %1, %2;" : "=r"(r) : "f"(hi), "f"(lo));
    return r;
}

// ---------------- init ----------------
__global__ void init_kernel() {
    int i = blockIdx.x * blockDim.x + threadIdx.x;
    if (i < Kk * Dd) g_upd[i] = 0.f;
    if (i < Nn) g_negsum[i] = 0.f;
    if (i < Kk) { g_rowsum[i] = 0.f; g_w2[i] = 0.f; }
    if (i == 0) g_pconsum = 0.f;
}

// ---------------- bf16 HMMA GEMM + fused epilogue ----------------
// C[n,k] = sum_d A[n,d]*B[k,d]. BM=128, BK=32, 256 thr (8 warps: 4M x 2N).
// CTA covers columns [bn0, bn0 + NT*16). Smem rows padded to 80B stride.
template <int PHASE, int NT>
__global__ void __launch_bounds__(256, 2) tgemm_kernel(
    const float* __restrict__ A, const float* __restrict__ Bm,
    const int* __restrict__ labels, int bn0)
{
    constexpr int NTC = NT * 16;         // columns per CTA (160 or 80)
    constexpr int ASZ = 128 * 80;        // bytes per A buffer
    constexpr int BSZ = NTC * 80;
    constexpr int BUF = ASZ + BSZ;
    constexpr int BSLOTS = NTC * 2;      // 16-float slots in B tile

    extern __shared__ char sm_raw[];
    char* smc = sm_raw;
    const uint32_t sbase = (uint32_t)__cvta_generic_to_shared(smc);
    const int tid = threadIdx.x;
    const int bm = blockIdx.x * 128;
    const int lane = tid & 31, wid = tid >> 5;
    const int wm = wid >> 1, wn = wid & 1;

    float acc[2][NT][4];
#pragma unroll
    for (int m = 0; m < 2; m++)
#pragma unroll
        for (int j = 0; j < NT; j++)
#pragma unroll
            for (int q = 0; q < 4; q++) acc[m][j][q] = 0.f;

    uint32_t pa[8], pb[16];
    const int arow = tid >> 1, ahalf = tid & 1;
    const bool aok = (bm + arow) < Nn;
    const float* Abase = A + (size_t)(bm + arow) * Dd + ahalf * 16;

    // ---- prefetch chunk into regs (fp32 -> bf16x2) ----
    auto ldg = [&](int ch) {
        const float* src = Abase + ch * 32;
#pragma unroll
        for (int i = 0; i < 4; i++) {
            float4 v = aok ? *(const float4*)(src + 4 * i) : make_float4(0.f, 0.f, 0.f, 0.f);
            pa[2 * i] = pack2(v.x, v.y); pa[2 * i + 1] = pack2(v.z, v.w);
        }
#pragma unroll
        for (int s = 0; s < 2; s++) {
            int idx = tid + 256 * s;
            if (idx < BSLOTS) {
                int br = idx >> 1, bh = idx & 1;
                const float* bs = Bm + (size_t)(bn0 + br) * Dd + ch * 32 + bh * 16;
#pragma unroll
                for (int i = 0; i < 4; i++) {
                    float4 v = *(const float4*)(bs + 4 * i);
                    pb[8 * s + 2 * i] = pack2(v.x, v.y);
                    pb[8 * s + 2 * i + 1] = pack2(v.z, v.w);
                }
            }
        }
    };
    auto sts = [&](int b) {
        char* d = smc + b * BUF + arow * 80 + ahalf * 32;
        *(uint4*)d = make_uint4(pa[0], pa[1], pa[2], pa[3]);
        *(uint4*)(d + 16) = make_uint4(pa[4], pa[5], pa[6], pa[7]);
#pragma unroll
        for (int s = 0; s < 2; s++) {
            int idx = tid + 256 * s;
            if (idx < BSLOTS) {
                int br = idx >> 1, bh = idx & 1;
                char* db = smc + b * BUF + ASZ + br * 80 + bh * 32;
                *(uint4*)db = make_uint4(pb[8*s+0], pb[8*s+1], pb[8*s+2], pb[8*s+3]);
                *(uint4*)(db + 16) = make_uint4(pb[8*s+4], pb[8*s+5], pb[8*s+6], pb[8*s+7]);
            }
        }
    };
    auto compute = [&](int b) {
        const uint32_t sA = sbase + b * BUF;
        const uint32_t sB = sA + ASZ;
#pragma unroll
        for (int kf = 0; kf < 2; kf++) {
            uint32_t af[2][4];
#pragma unroll
            for (int m = 0; m < 2; m++) {
                uint32_t ad = sA + (wm * 32 + m * 16 + (lane & 15)) * 80
                            + (kf * 16 + (lane >> 4) * 8) * 2;
                asm volatile("ldmatrix.sync.aligned.m8n8.x4.shared.b16 {%0,%1,%2,%3},[%4];"
                    : "=r"(af[m][0]), "=r"(af[m][1]), "=r"(af[m][2]), "=r"(af[m][3])
                    : "r"(ad));
            }
            const int lq = lane & 15;
#pragma unroll
            for (int j = 0; j < NT; j++) {
                uint32_t bd = sB + (wn * NT * 8 + j * 8 + (lq & 7)) * 80
                            + (kf * 16 + (lq >> 3) * 8) * 2;
                uint32_t b0, b1;
                asm volatile("ldmatrix.sync.aligned.m8n8.x2.shared.b16 {%0,%1},[%2];"
                    : "=r"(b0), "=r"(b1) : "r"(bd));
#pragma unroll
                for (int m = 0; m < 2; m++)
                    asm volatile(
                        "mma.sync.aligned.m16n8k16.row.col.f32.bf16.bf16.f32 "
                        "{%0,%1,%2,%3},{%4,%5,%6,%7},{%8,%9},{%0,%1,%2,%3};"
                        : "+f"(acc[m][j][0]), "+f"(acc[m][j][1]),
                          "+f"(acc[m][j][2]), "+f"(acc[m][j][3])
                        : "r"(af[m][0]), "r"(af[m][1]), "r"(af[m][2]), "r"(af[m][3]),
                          "r"(b0), "r"(b1));
            }
        }
    };

    ldg(0); sts(0); __syncthreads();
#pragma unroll 1
    for (int ch = 0; ch < 16; ch++) {
        if (ch < 15) ldg(ch + 1);
        compute(ch & 1);
        if (ch < 15) sts((ch + 1) & 1);
        __syncthreads();
    }

    // ---------------- fused epilogue ----------------
    float* colacc = (float*)smc;     // reuse smem
    for (int i = tid; i < NTC; i += 256) colacc[i] = 0.f;
    __syncthreads();

    const int cb = bn0 + wn * NT * 8;
    int rr[2][2], lb[2][2];
    bool ok[2][2];
#pragma unroll
    for (int m = 0; m < 2; m++)
#pragma unroll
        for (int h = 0; h < 2; h++) {
            int r = bm + wm * 32 + m * 16 + h * 8 + (lane >> 2);
            rr[m][h] = r; ok[m][h] = r < Nn;
            lb[m][h] = ok[m][h] ? labels[r] : -1;
        }
    float nacc[2][2] = {{0.f, 0.f}, {0.f, 0.f}};

#pragma unroll
    for (int j = 0; j < NT; j++) {
        const int c0 = cb + j * 8 + (lane & 3) * 2;
        const int km = c0 % 100;
        const int kd = c0 / 100;
        float cs0 = 0.f, cs1 = 0.f;
#pragma unroll
        for (int m = 0; m < 2; m++)
#pragma unroll
            for (int h = 0; h < 2; h++) {
                float v0 = acc[m][j][2 * h], v1 = acc[m][j][2 * h + 1];
                float e0, e1;
                if (PHASE == 1) {
                    e0 = __expf(20.f * v0); e1 = __expf(20.f * v1);
                } else {
                    float x0 = __expf(10.f * v0), x1 = __expf(10.f * v1);
                    if (ok[m][h]) nacc[m][h] += x0 + x1;
                    e0 = x0 * x0; e1 = x1 * x1;
                }
                if (ok[m][h]) {
                    int r = rr[m][h];
                    *(float2*)&g_E[(size_t)r * Kk + c0] = make_float2(e0, e1);
                    if (PHASE == 1) {
                        if (km == lb[m][h])     g_e4[r * 4 + kd] = e0;
                        if (km + 1 == lb[m][h]) g_e4[r * 4 + kd] = e1;
                    } else {
                        if (km == lb[m][h])     g_c4[r * 4 + kd] = v0;
                        if (km + 1 == lb[m][h]) g_c4[r * 4 + kd] = v1;
                    }
                    cs0 += e0; cs1 += e1;
                }
            }
#pragma unroll
        for (int o = 4; o <= 16; o <<= 1) {
            cs0 += __shfl_xor_sync(0xffffffffu, cs0, o);
            cs1 += __shfl_xor_sync(0xffffffffu, cs1, o);
        }
        if (lane < 4) {
            atomicAdd(&colacc[wn * NT * 8 + j * 8 + lane * 2], cs0);
            atomicAdd(&colacc[wn * NT * 8 + j * 8 + lane * 2 + 1], cs1);
        }
    }
    if (PHASE == 2) {
#pragma unroll
        for (int m = 0; m < 2; m++)
#pragma unroll
            for (int h = 0; h < 2; h++) {
                float v = nacc[m][h];
                v += __shfl_xor_sync(0xffffffffu, v, 1);
                v += __shfl_xor_sync(0xffffffffu, v, 2);
                if ((lane & 3) == 0 && ok[m][h]) atomicAdd(&g_negsum[rr[m][h]], v);
            }
    }
    __syncthreads();
    for (int i = tid; i < NTC; i += 256) atomicAdd(&g_rowsum[bn0 + i], colacc[i]);
}

// ---------------- alpha[k] = 1/(K * rowsum[k]); reset rowsum ----------------
__global__ void alpha_kernel() {
    int k = blockIdx.x * blockDim.x + threadIdx.x;
    if (k < Kk) {
        float rs = g_rowsum[k];
        g_alpha[k] = 1.f / (400.f * fmaxf(rs, 1e-12f));
        g_rowsum[k] = 0.f;
    }
}

// ---------------- fused Sinkhorn pass: col-normalize step + next row-sum ----------
__global__ void __launch_bounds__(256) sink_pass(const float* __restrict__ E,
                                                 float* __restrict__ rowsum_out) {
    __shared__ float s_alpha[Kk];
    __shared__ float s_acc[Kk];
    for (int i = threadIdx.x; i < Kk; i += 256) { s_alpha[i] = g_alpha[i]; s_acc[i] = 0.f; }
    __syncthreads();

    const int lane = threadIdx.x & 31;
    const int warp = threadIdx.x >> 5;
    const int gw = blockIdx.x * 8 + warp;
    float racc[13];
#pragma unroll
    for (int j = 0; j < 13; j++) racc[j] = 0.f;

    const int n0 = gw * 8;
    for (int r = 0; r < 8; r++) {
        int n = n0 + r;
        if (n >= Nn) break;
        const float* row = E + (size_t)n * Kk;
        float e[13];
        float s = 0.f;
#pragma unroll
        for (int j = 0; j < 13; j++) {
            int k = lane + 32 * j;
            float v = (k < Kk) ? row[k] : 0.f;
            e[j] = v;
            s += v * ((k < Kk) ? s_alpha[k] : 0.f);
        }
#pragma unroll
        for (int o = 16; o; o >>= 1) s += __shfl_xor_sync(0xffffffffu, s, o);
        float beta = 1.f / ((float)Nn * fmaxf(s, 1e-30f));
#pragma unroll
        for (int j = 0; j < 13; j++) racc[j] = fmaf(e[j], beta, racc[j]);
    }
#pragma unroll
    for (int j = 0; j < 13; j++) {
        int k = lane + 32 * j;
        if (k < Kk) atomicAdd(&s_acc[k], racc[j]);
    }
    __syncthreads();
    for (int i = threadIdx.x; i < Kk; i += 256) atomicAdd(&rowsum_out[i], s_acc[i]);
}

// ---------------- per-sample transport coeffs + column sums w2 ----------------
__global__ void coeff_kernel(const int* __restrict__ labels) {
    __shared__ float sacc[Kk];
    for (int i = threadIdx.x; i < Kk; i += blockDim.x) sacc[i] = 0.f;
    __syncthreads();
    int n = blockIdx.x * blockDim.x + threadIdx.x;
    int l = 0;
    float c4[4] = {0.f, 0.f, 0.f, 0.f};
    if (n < Nn) {
        l = labels[n];
        float q[4], s = 0.f;
        float4 e4 = *(const float4*)&g_e4[n * 4];
        float ev[4] = {e4.x, e4.y, e4.z, e4.w};
#pragma unroll
        for (int p = 0; p < 4; p++) {
            q[p] = g_alpha[l + 100 * p] * ev[p];
            s += q[p];
        }
        float inv = 1.f / fmaxf(s, 1e-30f);
#pragma unroll
        for (int p = 0; p < 4; p++) {
            float c = q[p] * inv;
            c4[p] = c;
            g_coeff[n * 4 + p] = c;
        }
#pragma unroll
        for (int p = 0; p < 4; p++) atomicAdd(&sacc[l + 100 * p], c4[p]);
    }
    __syncthreads();
    for (int i = threadIdx.x; i < Kk; i += blockDim.x) atomicAdd(&g_w2[i], sacc[i]);
}

// ---------------- scatter: upd[k,d] += (coeff/w2[k]) * f[n,d] ----------------
__global__ void __launch_bounds__(256) scatter_kernel(const float* __restrict__ feats,
                                                      const int* __restrict__ labels,
                                                      int nchunks) {
    extern __shared__ float sm[];
    float* acc = sm;               // 400*64
    float* winv = sm + 400 * 64;   // 400
    const int tid = threadIdx.x;
    for (int i = tid; i < 400 * 64; i += 256) acc[i] = 0.f;
    for (int i = tid; i < Kk; i += 256) winv[i] = 1.f / fmaxf(g_w2[i], 1e-12f);
    __syncthreads();

    const int d = tid & 63;
    const int sub = tid >> 6;
    const int d0 = blockIdx.x * 64;
    const int CH = (Nn + nchunks - 1) / nchunks;
    const int nb = blockIdx.y * CH;
    const int ne = (nb + CH < Nn) ? (nb + CH) : Nn;

    for (int n = nb; n < ne; n++) {
        int l = labels[n];
        float f = feats[(size_t)n * Dd + d0 + d];
        int k = l + 100 * sub;
        float c = g_coeff[n * 4 + sub] * winv[k];
        acc[k * 64 + d] += c * f;
    }
    __syncthreads();
    for (int i = tid; i < 400 * 64; i += 256)
        atomicAdd(&g_upd[(i >> 6) * Dd + d0 + (i & 63)], acc[i]);
}

// ---------------- protos_new = l2norm(0.99*protos + 0.01*upd) ----------------
__global__ void pnew_kernel(const float* __restrict__ protos) {
    int k = blockIdx.x;
    int tid = threadIdx.x;  // 128
    float v[4];
    float ss = 0.f;
#pragma unroll
    for (int j = 0; j < 4; j++) {
        int di = tid + 128 * j;
        float x = 0.99f * protos[k * Dd + di] + 0.01f * g_upd[k * Dd + di];
        v[j] = x;
        ss += x * x;
    }
    __shared__ float red[4];
#pragma unroll
    for (int o = 16; o; o >>= 1) ss += __shfl_xor_sync(0xffffffffu, ss, o);
    if ((tid & 31) == 0) red[tid >> 5] = ss;
    __syncthreads();
    float tot = red[0] + red[1] + red[2] + red[3];
    float inv = 1.f / fmaxf(sqrtf(tot), 1e-12f);
#pragma unroll
    for (int j = 0; j < 4; j++)
        g_pn[k * Dd + tid + 128 * j] = v[j] * inv;
}

// ---------------- small SIMT GEMM for adc = pn @ pn.T (400x400x512) ----------
__global__ void __launch_bounds__(256) adc_gemm(const float* __restrict__ A,
                                                const float* __restrict__ Bm,
                                                float* __restrict__ Cb, int Mr, int Nc)
{
    __shared__ float As[16][128];
    __shared__ float Bs[16][64];
    const int tid = threadIdx.x;
    const int bm = blockIdx.y * 128;
    const int bn = blockIdx.x * 64;
    const int tx = tid & 15;
    const int ty = tid >> 4;

    float acc[8][4];
#pragma unroll
    for (int i = 0; i < 8; i++)
#pragma unroll
        for (int j = 0; j < 4; j++) acc[i][j] = 0.f;

    const int alr = tid >> 1, alc = (tid & 1) * 8;
    const int blr = tid >> 2, blc = (tid & 3) * 4;
    const bool arow_ok = (bm + alr) < Mr;
    const bool brow_ok = (bn + blr) < Nc;
    const float* Aptr = A + (size_t)(bm + alr) * Dd + alc;
    const float* Bptr = Bm + (size_t)(bn + blr) * Dd + blc;

    for (int dk = 0; dk < Dd; dk += 16) {
        float4 a0 = {0,0,0,0}, a1 = {0,0,0,0}, b0 = {0,0,0,0};
        if (arow_ok) {
            a0 = *(const float4*)(Aptr + dk);
            a1 = *(const float4*)(Aptr + dk + 4);
        }
        if (brow_ok) b0 = *(const float4*)(Bptr + dk);
        As[alc + 0][alr] = a0.x; As[alc + 1][alr] = a0.y;
        As[alc + 2][alr] = a0.z; As[alc + 3][alr] = a0.w;
        As[alc + 4][alr] = a1.x; As[alc + 5][alr] = a1.y;
        As[alc + 6][alr] = a1.z; As[alc + 7][alr] = a1.w;
        Bs[blc + 0][blr] = b0.x; Bs[blc + 1][blr] = b0.y;
        Bs[blc + 2][blr] = b0.z; Bs[blc + 3][blr] = b0.w;
        __syncthreads();
#pragma unroll
        for (int dd = 0; dd < 16; dd++) {
            float4 av0 = *(const float4*)&As[dd][ty * 8];
            float4 av1 = *(const float4*)&As[dd][ty * 8 + 4];
            float4 bv  = *(const float4*)&Bs[dd][tx * 4];
            float ar[8] = {av0.x, av0.y, av0.z, av0.w, av1.x, av1.y, av1.z, av1.w};
            float br[4] = {bv.x, bv.y, bv.z, bv.w};
#pragma unroll
            for (int i = 0; i < 8; i++)
#pragma unroll
                for (int j = 0; j < 4; j++)
                    acc[i][j] = fmaf(ar[i], br[j], acc[i][j]);
        }
        __syncthreads();
    }
#pragma unroll
    for (int i = 0; i < 8; i++) {
        int n = bm + ty * 8 + i;
        if (n >= Mr) continue;
#pragma unroll
        for (int j = 0; j < 4; j++) {
            int k = bn + tx * 4 + j;
            if (k < Nc) Cb[(size_t)n * Kk + k] = acc[i][j];
        }
    }
}

// ---------------- proto contrast: one block per proto row ----------------
__global__ void pcon_kernel() {
    int k = blockIdx.x;
    int tid = threadIdx.x;  // 128
    const float* row = g_adc + k * Kk;
    __shared__ float rbuf[4];
    __shared__ float mxs;

    float mx = -1e30f;
    for (int j = tid; j < Kk; j += 128) mx = fmaxf(mx, 2.f * row[j]);
#pragma unroll
    for (int o = 16; o; o >>= 1) mx = fmaxf(mx, __shfl_xor_sync(0xffffffffu, mx, o));
    if ((tid & 31) == 0) rbuf[tid >> 5] = mx;
    __syncthreads();
    if (tid == 0) mxs = fmaxf(fmaxf(rbuf[0], rbuf[1]), fmaxf(rbuf[2], rbuf[3]));
    __syncthreads();
    mx = mxs;

    float se = 0.f, pp = 0.f;
    int cls = k % 100;
    for (int j = tid; j < Kk; j += 128) {
        float lg = 2.f * row[j] - mx;
        if (j != k) {
            se += __expf(lg);
            if (j % 100 == cls) pp += lg;
        }
    }
#pragma unroll
    for (int o = 16; o; o >>= 1) {
        se += __shfl_xor_sync(0xffffffffu, se, o);
        pp += __shfl_xor_sync(0xffffffffu, pp, o);
    }
    __shared__ float sbuf[4], pbuf[4];
    if ((tid & 31) == 0) { sbuf[tid >> 5] = se; pbuf[tid >> 5] = pp; }
    __syncthreads();
    if (tid == 0) {
        float sT = sbuf[0] + sbuf[1] + sbuf[2] + sbuf[3];
        float pT = pbuf[0] + pbuf[1] + pbuf[2] + pbuf[3];
        atomicAdd(&g_pconsum, pT * (1.f / 3.f) - logf(sT));
    }
}

// ---------------- final per-sample loss ----------------
__global__ void final_kernel(const int* __restrict__ labels, float* __restrict__ out) {
    int n = blockIdx.x * blockDim.x + threadIdx.x;
    if (n >= Nn) return;
    int l = labels[n];
    float4 cc = *(const float4*)&g_c4[n * 4];
    float cv[4] = {cc.x, cc.y, cc.z, cc.w};
    float num = 0.f, den = 0.f;
#pragma unroll
    for (int p = 0; p < 4; p++) {
        float c = cv[p];
        float q = g_alpha[l + 100 * p] * __expf(20.f * c);
        num += q * (10.f * c);
        den += q;
    }
    float pos = num / fmaxf(den, 1e-30f);
    float neg = logf(g_negsum[n]);
    float pcon = -g_pconsum * (1.f / 400.f);
    out[n] = -(pos - neg) + pcon;
}

// ---------------- launch ----------------
extern "C" void kernel_launch(void* const* d_in, const int* in_sizes, int n_in,
                              void* d_out, int out_size) {
    const float* feats  = (const float*)d_in[0];
    const float* protos = (const float*)d_in[1];
    const int*   labels = (const int*)d_in[2];
    float* out = (float*)d_out;

    float *pE, *pPN, *pADC, *pRS;
    cudaGetSymbolAddress((void**)&pE,  g_E);
    cudaGetSymbolAddress((void**)&pPN, g_pn);
    cudaGetSymbolAddress((void**)&pADC, g_adc);
    cudaGetSymbolAddress((void**)&pRS, g_rowsum);

    const int SMEM_SCATTER = (400 * 64 + 400) * 4;
    cudaFuncSetAttribute(scatter_kernel, cudaFuncAttributeMaxDynamicSharedMemorySize,
                         SMEM_SCATTER);
    const int SMEM10 = 2 * (128 * 80 + 160 * 80);   // 46080
    const int SMEM5  = 2 * (128 * 80 +  80 * 80);   // 33280
    cudaFuncSetAttribute(tgemm_kernel<1, 10>, cudaFuncAttributeMaxDynamicSharedMemorySize, SMEM10);
    cudaFuncSetAttribute(tgemm_kernel<2, 10>, cudaFuncAttributeMaxDynamicSharedMemorySize, SMEM10);
    cudaFuncSetAttribute(tgemm_kernel<1, 5>,  cudaFuncAttributeMaxDynamicSharedMemorySize, SMEM5);
    cudaFuncSetAttribute(tgemm_kernel<2, 5>,  cudaFuncAttributeMaxDynamicSharedMemorySize, SMEM5);

    init_kernel<<<(Kk * Dd + 255) / 256, 256>>>();

    const int NB = (Nn + 127) / 128;   // 782

    // ---------- phase 1: E1 = exp(20*feats@protos^T), rowsum, e4 ----------
    tgemm_kernel<1, 10><<<NB, 256, SMEM10>>>(feats, protos, labels, 0);
    tgemm_kernel<1, 10><<<NB, 256, SMEM10>>>(feats, protos, labels, 160);
    tgemm_kernel<1, 5><<<NB, 256, SMEM5>>>(feats, protos, labels, 320);
    alpha_kernel<<<2, 256>>>();
    sink_pass<<<(Nn + 63) / 64, 256>>>(pE, pRS);
    alpha_kernel<<<2, 256>>>();
    sink_pass<<<(Nn + 63) / 64, 256>>>(pE, pRS);
    alpha_kernel<<<2, 256>>>();

    coeff_kernel<<<(Nn + 255) / 256, 256>>>(labels);
    {
        dim3 gs(8, 32);
        scatter_kernel<<<gs, 256, SMEM_SCATTER>>>(feats, labels, 32);
    }
    pnew_kernel<<<Kk, 128>>>(protos);

    // ---------- phase 2: E2, c4, negsum vs protos_new ----------
    tgemm_kernel<2, 10><<<NB, 256, SMEM10>>>(feats, pPN, labels, 0);
    tgemm_kernel<2, 10><<<NB, 256, SMEM10>>>(feats, pPN, labels, 160);
    tgemm_kernel<2, 5><<<NB, 256, SMEM5>>>(feats, pPN, labels, 320);
    alpha_kernel<<<2, 256>>>();
    sink_pass<<<(Nn + 63) / 64, 256>>>(pE, pRS);
    alpha_kernel<<<2, 256>>>();
    sink_pass<<<(Nn + 63) / 64, 256>>>(pE, pRS);
    alpha_kernel<<<2, 256>>>();

    // ---------- proto contrast ----------
    {
        dim3 ga((Kk + 63) / 64, (Kk + 127) / 128);
        adc_gemm<<<ga, 256>>>(pPN, pPN, pADC, Kk, Kk);
    }
    pcon_kernel<<<Kk, 128>>>();

    final_kernel<<<(Nn + 255) / 256, 256>>>(labels, out);
}

// round 10
// speedup vs baseline: 2.2747x; 1.5567x over previous
#include <cuda_runtime.h>
#include <cuda_bf16.h>
#include <math.h>
#include <stdint.h>

#define Nn 100000
#define Dd 512
#define Kk 400

// ---------------- scratch (device globals; no allocation allowed) ----------------
__device__ float g_E[(size_t)Nn * Kk];     // exp(C/eps) for current phase (160MB)
__device__ float g_alpha[Kk];
__device__ float g_rowsum[Kk];
__device__ float g_w2[Kk];
__device__ float g_coeff[Nn * 4];
__device__ float g_upd[Kk * Dd];
__device__ float g_pn[Kk * Dd];
__device__ __nv_bfloat16 g_pbf[Kk * Dd];   // bf16 B operand (protos, then protos_new)
__device__ float g_negsum[Nn];
__device__ float g_adc[Kk * Kk];
__device__ float g_e4[Nn * 4];             // phase1 E at the 4 class protos
__device__ float g_c4[Nn * 4];             // phase2 raw cosine at the 4 class protos
__device__ float g_pconsum;

__device__ __forceinline__ uint32_t pack2(float lo, float hi) {
    uint32_t r;
    asm("cvt.rn.bf16x2.f32 %0, %1, %2;" : "=r"(r) : "f"(hi), "f"(lo));
    return r;
}

// ---------------- init ----------------
__global__ void init_kernel() {
    int i = blockIdx.x * blockDim.x + threadIdx.x;
    if (i < Kk * Dd) g_upd[i] = 0.f;
    if (i < Nn) g_negsum[i] = 0.f;
    if (i < Kk) { g_rowsum[i] = 0.f; g_w2[i] = 0.f; }
    if (i == 0) g_pconsum = 0.f;
}

// ---------------- fp32 -> bf16 B pre-convert ----------------
__global__ void convB_kernel(const float* __restrict__ src) {
    int i = blockIdx.x * blockDim.x + threadIdx.x;   // 51200 float4 slots
    if (i < Kk * Dd / 4) {
        float4 v = ((const float4*)src)[i];
        reinterpret_cast<uint2*>(g_pbf)[i] = make_uint2(pack2(v.x, v.y), pack2(v.z, v.w));
    }
}

// ---------------- A-resident bf16 HMMA GEMM + fused epilogue ----------------
// C[n,k] = sum_d A[n,d]*B[k,d]. BM=192 rows/CTA, A (192x512 bf16) resident in smem.
// 5 N-tiles of 80 cols; B chunks (80x64 bf16) double-buffered.
// 256 thr = 8 warps: wm 0..3 (48 rows, 3 m16 tiles), wn 0..1 (40 cols, 5 n8 tiles).
template <int PHASE>
__global__ void __launch_bounds__(256, 1) tgemm_kernel(
    const float* __restrict__ A, const int* __restrict__ labels)
{
    constexpr int BM  = 192;
    constexpr int AST = 1040;             // A smem row stride (512*2 + 16 pad)
    constexpr int BST = 144;              // B smem row stride (64*2 + 16 pad)
    constexpr int ASZ = BM * AST;         // 199680
    constexpr int BBUF = 80 * BST;        // 11520

    extern __shared__ char smc[];
    char* smA = smc;
    char* smB = smc + ASZ;
    float* colacc = (float*)(smc + ASZ + 2 * BBUF);

    const uint32_t sAu = (uint32_t)__cvta_generic_to_shared(smA);
    const uint32_t sBu = sAu + ASZ;

    const int tid = threadIdx.x;
    const int bm = blockIdx.x * BM;
    const int lane = tid & 31, wid = tid >> 5;
    const int wm = wid >> 1, wn = wid & 1;

    // ---- load + convert A tile: BM x 512 fp32 -> bf16 smem (resident) ----
#pragma unroll 4
    for (int it = 0; it < 48; it++) {
        int slot = tid + 256 * it;        // 12288 slots, 8 halves each
        int row = slot >> 6, c = slot & 63;
        bool ok = (bm + row) < Nn;
        const float* src = A + (size_t)(bm + row) * Dd + c * 8;
        float4 v0 = ok ? *(const float4*)src : make_float4(0.f, 0.f, 0.f, 0.f);
        float4 v1 = ok ? *(const float4*)(src + 4) : make_float4(0.f, 0.f, 0.f, 0.f);
        *(uint4*)(smA + row * AST + c * 16) =
            make_uint4(pack2(v0.x, v0.y), pack2(v0.z, v0.w),
                       pack2(v1.x, v1.y), pack2(v1.z, v1.w));
    }

    // per-thread epilogue row info (rows fixed across N-tiles)
    int rr[3][2], lb[3][2];
    bool ok[3][2];
#pragma unroll
    for (int m = 0; m < 3; m++)
#pragma unroll
        for (int h = 0; h < 2; h++) {
            int r = bm + wm * 48 + m * 16 + h * 8 + (lane >> 2);
            rr[m][h] = r; ok[m][h] = r < Nn;
            lb[m][h] = ok[m][h] ? labels[r] : -1;
        }
    float nacc[3][2] = {{0.f, 0.f}, {0.f, 0.f}, {0.f, 0.f}};

    uint4 pb[3];
    auto ldgB = [&](int nt, int kc) {
#pragma unroll
        for (int it = 0; it < 3; it++) {
            int slot = tid + 256 * it;    // 640 slots: 80 rows x 8 x 16B
            if (slot < 640) {
                int row = slot >> 3, c = slot & 7;
                pb[it] = *(const uint4*)(g_pbf + (size_t)(nt * 80 + row) * Dd + kc * 64 + c * 8);
            }
        }
    };
    auto stsB = [&](int b) {
#pragma unroll
        for (int it = 0; it < 3; it++) {
            int slot = tid + 256 * it;
            if (slot < 640) {
                int row = slot >> 3, c = slot & 7;
                *(uint4*)(smB + b * BBUF + row * BST + c * 16) = pb[it];
            }
        }
    };

    float acc[3][5][4];

    auto compute = [&](int kc, int b) {
        const uint32_t sBb = sBu + b * BBUF;
#pragma unroll
        for (int kf = 0; kf < 4; kf++) {
            const int kk = kc * 4 + kf;
            uint32_t af[3][4];
#pragma unroll
            for (int m = 0; m < 3; m++) {
                uint32_t ad = sAu + (wm * 48 + m * 16 + (lane & 15)) * AST
                            + kk * 32 + (lane >> 4) * 16;
                asm volatile("ldmatrix.sync.aligned.m8n8.x4.shared.b16 {%0,%1,%2,%3},[%4];"
                    : "=r"(af[m][0]), "=r"(af[m][1]), "=r"(af[m][2]), "=r"(af[m][3])
                    : "r"(ad));
            }
            uint32_t bf[5][2];
            {
                const int g = lane >> 3;
                // tiles (0,1) via x4
                uint32_t bd = sBb + (wn * 40 + (0 + (g >> 1)) * 8 + (lane & 7)) * BST
                            + kf * 32 + (g & 1) * 16;
                asm volatile("ldmatrix.sync.aligned.m8n8.x4.shared.b16 {%0,%1,%2,%3},[%4];"
                    : "=r"(bf[0][0]), "=r"(bf[0][1]), "=r"(bf[1][0]), "=r"(bf[1][1])
                    : "r"(bd));
                // tiles (2,3) via x4
                uint32_t bd2 = sBb + (wn * 40 + (2 + (g >> 1)) * 8 + (lane & 7)) * BST
                             + kf * 32 + (g & 1) * 16;
                asm volatile("ldmatrix.sync.aligned.m8n8.x4.shared.b16 {%0,%1,%2,%3},[%4];"
                    : "=r"(bf[2][0]), "=r"(bf[2][1]), "=r"(bf[3][0]), "=r"(bf[3][1])
                    : "r"(bd2));
                // tile 4 via x2
                const int lq = lane & 15;
                uint32_t bd3 = sBb + (wn * 40 + 32 + (lq & 7)) * BST
                             + kf * 32 + (lq >> 3) * 16;
                asm volatile("ldmatrix.sync.aligned.m8n8.x2.shared.b16 {%0,%1},[%2];"
                    : "=r"(bf[4][0]), "=r"(bf[4][1]) : "r"(bd3));
            }
#pragma unroll
            for (int m = 0; m < 3; m++)
#pragma unroll
                for (int j = 0; j < 5; j++)
                    asm volatile(
                        "mma.sync.aligned.m16n8k16.row.col.f32.bf16.bf16.f32 "
                        "{%0,%1,%2,%3},{%4,%5,%6,%7},{%8,%9},{%0,%1,%2,%3};"
                        : "+f"(acc[m][j][0]), "+f"(acc[m][j][1]),
                          "+f"(acc[m][j][2]), "+f"(acc[m][j][3])
                        : "r"(af[m][0]), "r"(af[m][1]), "r"(af[m][2]), "r"(af[m][3]),
                          "r"(bf[j][0]), "r"(bf[j][1]));
        }
    };

#pragma unroll 1
    for (int nt = 0; nt < 5; nt++) {
        ldgB(nt, 0); stsB(0); __syncthreads();
#pragma unroll
        for (int m = 0; m < 3; m++)
#pragma unroll
            for (int j = 0; j < 5; j++)
#pragma unroll
                for (int q = 0; q < 4; q++) acc[m][j][q] = 0.f;

#pragma unroll 1
        for (int kc = 0; kc < 8; kc++) {
            if (kc < 7) ldgB(nt, kc + 1);
            compute(kc, kc & 1);
            if (kc < 7) stsB((kc + 1) & 1);
            __syncthreads();
        }

        // ---- fused epilogue for this 80-column tile ----
        for (int i = tid; i < 80; i += 256) colacc[i] = 0.f;
        __syncthreads();
        const int cb = nt * 80 + wn * 40;
#pragma unroll
        for (int j = 0; j < 5; j++) {
            const int c0 = cb + j * 8 + (lane & 3) * 2;
            const int km = c0 % 100;
            const int kd = c0 / 100;
            float cs0 = 0.f, cs1 = 0.f;
#pragma unroll
            for (int m = 0; m < 3; m++)
#pragma unroll
                for (int h = 0; h < 2; h++) {
                    float v0 = acc[m][j][2 * h], v1 = acc[m][j][2 * h + 1];
                    float e0, e1;
                    if (PHASE == 1) {
                        e0 = __expf(20.f * v0); e1 = __expf(20.f * v1);
                    } else {
                        float x0 = __expf(10.f * v0), x1 = __expf(10.f * v1);
                        if (ok[m][h]) nacc[m][h] += x0 + x1;
                        e0 = x0 * x0; e1 = x1 * x1;
                    }
                    if (ok[m][h]) {
                        int r = rr[m][h];
                        *(float2*)&g_E[(size_t)r * Kk + c0] = make_float2(e0, e1);
                        if (PHASE == 1) {
                            if (km == lb[m][h])     g_e4[r * 4 + kd] = e0;
                            if (km + 1 == lb[m][h]) g_e4[r * 4 + kd] = e1;
                        } else {
                            if (km == lb[m][h])     g_c4[r * 4 + kd] = v0;
                            if (km + 1 == lb[m][h]) g_c4[r * 4 + kd] = v1;
                        }
                        cs0 += e0; cs1 += e1;
                    }
                }
#pragma unroll
            for (int o = 4; o <= 16; o <<= 1) {
                cs0 += __shfl_xor_sync(0xffffffffu, cs0, o);
                cs1 += __shfl_xor_sync(0xffffffffu, cs1, o);
            }
            if (lane < 4) {
                atomicAdd(&colacc[wn * 40 + j * 8 + lane * 2], cs0);
                atomicAdd(&colacc[wn * 40 + j * 8 + lane * 2 + 1], cs1);
            }
        }
        __syncthreads();
        for (int i = tid; i < 80; i += 256) atomicAdd(&g_rowsum[nt * 80 + i], colacc[i]);
        __syncthreads();
    }

    if (PHASE == 2) {
#pragma unroll
        for (int m = 0; m < 3; m++)
#pragma unroll
            for (int h = 0; h < 2; h++) {
                float v = nacc[m][h];
                v += __shfl_xor_sync(0xffffffffu, v, 1);
                v += __shfl_xor_sync(0xffffffffu, v, 2);
                if ((lane & 3) == 0 && ok[m][h]) atomicAdd(&g_negsum[rr[m][h]], v);
            }
    }
}

// ---------------- alpha[k] = 1/(K * rowsum[k]); reset rowsum ----------------
__global__ void alpha_kernel() {
    int k = blockIdx.x * blockDim.x + threadIdx.x;
    if (k < Kk) {
        float rs = g_rowsum[k];
        g_alpha[k] = 1.f / (400.f * fmaxf(rs, 1e-12f));
        g_rowsum[k] = 0.f;
    }
}

// ---------------- fused Sinkhorn pass: col-normalize step + next row-sum ----------
__global__ void __launch_bounds__(256) sink_pass(const float* __restrict__ E,
                                                 float* __restrict__ rowsum_out) {
    __shared__ float4 s_alpha[100];
    __shared__ float s_acc[Kk];
    for (int i = threadIdx.x; i < 100; i += 256) s_alpha[i] = ((const float4*)g_alpha)[i];
    for (int i = threadIdx.x; i < Kk; i += 256) s_acc[i] = 0.f;
    __syncthreads();

    const int lane = threadIdx.x & 31;
    const int warp = threadIdx.x >> 5;
    const int n0 = (blockIdx.x * 8 + warp) * 8;

    float4 racc[4];
#pragma unroll
    for (int j = 0; j < 4; j++) racc[j] = make_float4(0.f, 0.f, 0.f, 0.f);

#pragma unroll 1
    for (int r = 0; r < 8; r++) {
        int n = n0 + r;
        if (n >= Nn) break;
        const float4* row = (const float4*)(E + (size_t)n * Kk);
        float4 e[4];
        float s = 0.f;
#pragma unroll
        for (int j = 0; j < 3; j++) {
            int idx = lane + 32 * j;
            e[j] = row[idx];
            float4 a = s_alpha[idx];
            s = fmaf(e[j].x, a.x, s); s = fmaf(e[j].y, a.y, s);
            s = fmaf(e[j].z, a.z, s); s = fmaf(e[j].w, a.w, s);
        }
        e[3] = make_float4(0.f, 0.f, 0.f, 0.f);
        if (lane < 4) {
            int idx = lane + 96;
            e[3] = row[idx];
            float4 a = s_alpha[idx];
            s = fmaf(e[3].x, a.x, s); s = fmaf(e[3].y, a.y, s);
            s = fmaf(e[3].z, a.z, s); s = fmaf(e[3].w, a.w, s);
        }
#pragma unroll
        for (int o = 16; o; o >>= 1) s += __shfl_xor_sync(0xffffffffu, s, o);
        float beta = 1.f / ((float)Nn * fmaxf(s, 1e-30f));
#pragma unroll
        for (int j = 0; j < 4; j++) {
            racc[j].x = fmaf(e[j].x, beta, racc[j].x);
            racc[j].y = fmaf(e[j].y, beta, racc[j].y);
            racc[j].z = fmaf(e[j].z, beta, racc[j].z);
            racc[j].w = fmaf(e[j].w, beta, racc[j].w);
        }
    }
#pragma unroll
    for (int j = 0; j < 4; j++) {
        int idx = lane + 32 * j;
        if (idx < 100) {
            atomicAdd(&s_acc[4 * idx + 0], racc[j].x);
            atomicAdd(&s_acc[4 * idx + 1], racc[j].y);
            atomicAdd(&s_acc[4 * idx + 2], racc[j].z);
            atomicAdd(&s_acc[4 * idx + 3], racc[j].w);
        }
    }
    __syncthreads();
    for (int i = threadIdx.x; i < Kk; i += 256) atomicAdd(&rowsum_out[i], s_acc[i]);
}

// ---------------- per-sample transport coeffs + column sums w2 ----------------
__global__ void coeff_kernel(const int* __restrict__ labels) {
    __shared__ float sacc[Kk];
    for (int i = threadIdx.x; i < Kk; i += blockDim.x) sacc[i] = 0.f;
    __syncthreads();
    int n = blockIdx.x * blockDim.x + threadIdx.x;
    int l = 0;
    float c4[4] = {0.f, 0.f, 0.f, 0.f};
    if (n < Nn) {
        l = labels[n];
        float q[4], s = 0.f;
        float4 e4 = *(const float4*)&g_e4[n * 4];
        float ev[4] = {e4.x, e4.y, e4.z, e4.w};
#pragma unroll
        for (int p = 0; p < 4; p++) {
            q[p] = g_alpha[l + 100 * p] * ev[p];
            s += q[p];
        }
        float inv = 1.f / fmaxf(s, 1e-30f);
#pragma unroll
        for (int p = 0; p < 4; p++) {
            float c = q[p] * inv;
            c4[p] = c;
            g_coeff[n * 4 + p] = c;
        }
#pragma unroll
        for (int p = 0; p < 4; p++) atomicAdd(&sacc[l + 100 * p], c4[p]);
    }
    __syncthreads();
    for (int i = threadIdx.x; i < Kk; i += blockDim.x) atomicAdd(&g_w2[i], sacc[i]);
}

// ---------------- scatter: upd[k,d] += (coeff/w2[k]) * f[n,d] ----------------
__global__ void __launch_bounds__(256) scatter_kernel(const float* __restrict__ feats,
                                                      const int* __restrict__ labels,
                                                      int nchunks) {
    extern __shared__ float sm[];
    float* acc = sm;               // 400*64
    float* winv = sm + 400 * 64;   // 400
    const int tid = threadIdx.x;
    for (int i = tid; i < 400 * 64; i += 256) acc[i] = 0.f;
    for (int i = tid; i < Kk; i += 256) winv[i] = 1.f / fmaxf(g_w2[i], 1e-12f);
    __syncthreads();

    const int d = tid & 63;
    const int sub = tid >> 6;
    const int d0 = blockIdx.x * 64;
    const int CH = (Nn + nchunks - 1) / nchunks;
    const int nb = blockIdx.y * CH;
    const int ne = (nb + CH < Nn) ? (nb + CH) : Nn;

    for (int n = nb; n < ne; n++) {
        int l = labels[n];
        float f = feats[(size_t)n * Dd + d0 + d];
        int k = l + 100 * sub;
        float c = g_coeff[n * 4 + sub] * winv[k];
        acc[k * 64 + d] += c * f;
    }
    __syncthreads();
    for (int i = tid; i < 400 * 64; i += 256)
        atomicAdd(&g_upd[(i >> 6) * Dd + d0 + (i & 63)], acc[i]);
}

// ---------------- protos_new = l2norm(0.99*protos + 0.01*upd); fp32 + bf16 ------
__global__ void pnew_kernel(const float* __restrict__ protos) {
    int k = blockIdx.x;
    int tid = threadIdx.x;  // 128
    float v[4];
    float ss = 0.f;
#pragma unroll
    for (int j = 0; j < 4; j++) {
        int di = tid + 128 * j;
        float x = 0.99f * protos[k * Dd + di] + 0.01f * g_upd[k * Dd + di];
        v[j] = x;
        ss += x * x;
    }
    __shared__ float red[4];
#pragma unroll
    for (int o = 16; o; o >>= 1) ss += __shfl_xor_sync(0xffffffffu, ss, o);
    if ((tid & 31) == 0) red[tid >> 5] = ss;
    __syncthreads();
    float tot = red[0] + red[1] + red[2] + red[3];
    float inv = 1.f / fmaxf(sqrtf(tot), 1e-12f);
#pragma unroll
    for (int j = 0; j < 4; j++) {
        float y = v[j] * inv;
        g_pn[k * Dd + tid + 128 * j] = y;
        g_pbf[k * Dd + tid + 128 * j] = __float2bfloat16(y);
    }
}

// ---------------- small SIMT GEMM for adc = pn @ pn.T (400x400x512) ----------
__global__ void __launch_bounds__(256) adc_gemm(const float* __restrict__ A,
                                                const float* __restrict__ Bm,
                                                float* __restrict__ Cb, int Mr, int Nc)
{
    __shared__ float As[16][128];
    __shared__ float Bs[16][64];
    const int tid = threadIdx.x;
    const int bm = blockIdx.y * 128;
    const int bn = blockIdx.x * 64;
    const int tx = tid & 15;
    const int ty = tid >> 4;

    float acc[8][4];
#pragma unroll
    for (int i = 0; i < 8; i++)
#pragma unroll
        for (int j = 0; j < 4; j++) acc[i][j] = 0.f;

    const int alr = tid >> 1, alc = (tid & 1) * 8;
    const int blr = tid >> 2, blc = (tid & 3) * 4;
    const bool arow_ok = (bm + alr) < Mr;
    const bool brow_ok = (bn + blr) < Nc;
    const float* Aptr = A + (size_t)(bm + alr) * Dd + alc;
    const float* Bptr = Bm + (size_t)(bn + blr) * Dd + blc;

    for (int dk = 0; dk < Dd; dk += 16) {
        float4 a0 = {0,0,0,0}, a1 = {0,0,0,0}, b0 = {0,0,0,0};
        if (arow_ok) {
            a0 = *(const float4*)(Aptr + dk);
            a1 = *(const float4*)(Aptr + dk + 4);
        }
        if (brow_ok) b0 = *(const float4*)(Bptr + dk);
        As[alc + 0][alr] = a0.x; As[alc + 1][alr] = a0.y;
        As[alc + 2][alr] = a0.z; As[alc + 3][alr] = a0.w;
        As[alc + 4][alr] = a1.x; As[alc + 5][alr] = a1.y;
        As[alc + 6][alr] = a1.z; As[alc + 7][alr] = a1.w;
        Bs[blc + 0][blr] = b0.x; Bs[blc + 1][blr] = b0.y;
        Bs[blc + 2][blr] = b0.z; Bs[blc + 3][blr] = b0.w;
        __syncthreads();
#pragma unroll
        for (int dd = 0; dd < 16; dd++) {
            float4 av0 = *(const float4*)&As[dd][ty * 8];
            float4 av1 = *(const float4*)&As[dd][ty * 8 + 4];
            float4 bv  = *(const float4*)&Bs[dd][tx * 4];
            float ar[8] = {av0.x, av0.y, av0.z, av0.w, av1.x, av1.y, av1.z, av1.w};
            float br[4] = {bv.x, bv.y, bv.z, bv.w};
#pragma unroll
            for (int i = 0; i < 8; i++)
#pragma unroll
                for (int j = 0; j < 4; j++)
                    acc[i][j] = fmaf(ar[i], br[j], acc[i][j]);
        }
        __syncthreads();
    }
#pragma unroll
    for (int i = 0; i < 8; i++) {
        int n = bm + ty * 8 + i;
        if (n >= Mr) continue;
#pragma unroll
        for (int j = 0; j < 4; j++) {
            int k = bn + tx * 4 + j;
            if (k < Nc) Cb[(size_t)n * Kk + k] = acc[i][j];
        }
    }
}

// ---------------- proto contrast: one block per proto row ----------------
__global__ void pcon_kernel() {
    int k = blockIdx.x;
    int tid = threadIdx.x;  // 128
    const float* row = g_adc + k * Kk;
    __shared__ float rbuf[4];
    __shared__ float mxs;

    float mx = -1e30f;
    for (int j = tid; j < Kk; j += 128) mx = fmaxf(mx, 2.f * row[j]);
#pragma unroll
    for (int o = 16; o; o >>= 1) mx = fmaxf(mx, __shfl_xor_sync(0xffffffffu, mx, o));
    if ((tid & 31) == 0) rbuf[tid >> 5] = mx;
    __syncthreads();
    if (tid == 0) mxs = fmaxf(fmaxf(rbuf[0], rbuf[1]), fmaxf(rbuf[2], rbuf[3]));
    __syncthreads();
    mx = mxs;

    float se = 0.f, pp = 0.f;
    int cls = k % 100;
    for (int j = tid; j < Kk; j += 128) {
        float lg = 2.f * row[j] - mx;
        if (j != k) {
            se += __expf(lg);
            if (j % 100 == cls) pp += lg;
        }
    }
#pragma unroll
    for (int o = 16; o; o >>= 1) {
        se += __shfl_xor_sync(0xffffffffu, se, o);
        pp += __shfl_xor_sync(0xffffffffu, pp, o);
    }
    __shared__ float sbuf[4], pbuf[4];
    if ((tid & 31) == 0) { sbuf[tid >> 5] = se; pbuf[tid >> 5] = pp; }
    __syncthreads();
    if (tid == 0) {
        float sT = sbuf[0] + sbuf[1] + sbuf[2] + sbuf[3];
        float pT = pbuf[0] + pbuf[1] + pbuf[2] + pbuf[3];
        atomicAdd(&g_pconsum, pT * (1.f / 3.f) - logf(sT));
    }
}

// ---------------- final per-sample loss ----------------
__global__ void final_kernel(const int* __restrict__ labels, float* __restrict__ out) {
    int n = blockIdx.x * blockDim.x + threadIdx.x;
    if (n >= Nn) return;
    int l = labels[n];
    float4 cc = *(const float4*)&g_c4[n * 4];
    float cv[4] = {cc.x, cc.y, cc.z, cc.w};
    float num = 0.f, den = 0.f;
#pragma unroll
    for (int p = 0; p < 4; p++) {
        float c = cv[p];
        float q = g_alpha[l + 100 * p] * __expf(20.f * c);
        num += q * (10.f * c);
        den += q;
    }
    float pos = num / fmaxf(den, 1e-30f);
    float neg = logf(g_negsum[n]);
    float pcon = -g_pconsum * (1.f / 400.f);
    out[n] = -(pos - neg) + pcon;
}

// ---------------- launch ----------------
extern "C" void kernel_launch(void* const* d_in, const int* in_sizes, int n_in,
                              void* d_out, int out_size) {
    const float* feats  = (const float*)d_in[0];
    const float* protos = (const float*)d_in[1];
    const int*   labels = (const int*)d_in[2];
    float* out = (float*)d_out;

    float *pE, *pPN, *pADC, *pRS;
    cudaGetSymbolAddress((void**)&pE,  g_E);
    cudaGetSymbolAddress((void**)&pPN, g_pn);
    cudaGetSymbolAddress((void**)&pADC, g_adc);
    cudaGetSymbolAddress((void**)&pRS, g_rowsum);

    const int SMEM_SCATTER = (400 * 64 + 400) * 4;
    cudaFuncSetAttribute(scatter_kernel, cudaFuncAttributeMaxDynamicSharedMemorySize,
                         SMEM_SCATTER);
    const int TG_SMEM = 192 * 1040 + 2 * 11520 + 320;   // 223040
    cudaFuncSetAttribute(tgemm_kernel<1>, cudaFuncAttributeMaxDynamicSharedMemorySize, TG_SMEM);
    cudaFuncSetAttribute(tgemm_kernel<2>, cudaFuncAttributeMaxDynamicSharedMemorySize, TG_SMEM);

    init_kernel<<<(Kk * Dd + 255) / 256, 256>>>();
    convB_kernel<<<(Kk * Dd / 4 + 255) / 256, 256>>>(protos);

    const int NB = (Nn + 191) / 192;   // 521

    // ---------- phase 1: E1 = exp(20*feats@protos^T), rowsum, e4 ----------
    tgemm_kernel<1><<<NB, 256, TG_SMEM>>>(feats, labels);
    alpha_kernel<<<2, 256>>>();
    sink_pass<<<(Nn + 63) / 64, 256>>>(pE, pRS);
    alpha_kernel<<<2, 256>>>();
    sink_pass<<<(Nn + 63) / 64, 256>>>(pE, pRS);
    alpha_kernel<<<2, 256>>>();

    coeff_kernel<<<(Nn + 255) / 256, 256>>>(labels);
    {
        dim3 gs(8, 64);
        scatter_kernel<<<gs, 256, SMEM_SCATTER>>>(feats, labels, 64);
    }
    pnew_kernel<<<Kk, 128>>>(protos);   // writes g_pn (fp32) + g_pbf (bf16)

    // ---------- phase 2: E2, c4, negsum vs protos_new ----------
    tgemm_kernel<2><<<NB, 256, TG_SMEM>>>(feats, labels);
    alpha_kernel<<<2, 256>>>();
    sink_pass<<<(Nn + 63) / 64, 256>>>(pE, pRS);
    alpha_kernel<<<2, 256>>>();
    sink_pass<<<(Nn + 63) / 64, 256>>>(pE, pRS);
    alpha_kernel<<<2, 256>>>();

    // ---------- proto contrast ----------
    {
        dim3 ga((Kk + 63) / 64, (Kk + 127) / 128);
        adc_gemm<<<ga, 256>>>(pPN, pPN, pADC, Kk, Kk);
    }
    pcon_kernel<<<Kk, 128>>>();

    final_kernel<<<(Nn + 255) / 256, 256>>>(labels, out);
}